// round 11
// baseline (speedup 1.0000x reference)
#include <cuda_runtime.h>

// CustomStrainEnergyLoss: mean over B of (trapz(y_pred - y_true, x, segments j < idx))^2
// Element-weight form: integral_r = sum_{j=0}^{idx_r} w(j)*(p[j]-t[j]),
//   w(j) = 0.5*((j>0 ? x[j]-x[j-1] : 0) + (j<idx ? x[j+1]-x[j] : 0))
// Interior j (j < idx): w(j) = 0.5*(x[j+1]-x[max(j-1,0)])  (clamp makes j=0 exact).
//
// ROUND 11: uniform-tile decomposition. Work unit = (row, 2048-elem chunk).
// Persistent-ish grid (1216 blocks) strides over all tiles: dead tiles (chunk
// past idx) exit in ~100cyc; live tiles are uniform streaming units -> no
// long-row tails, serial heads amortized over each block's whole lifetime.
// Per-row partial integrals accumulate in __device__ scratch; a final kernel
// squares and means them.

#define THREADS 256
#define CHUNK 2048                 // elements per tile
#define CHUNK_VEC (CHUNK / 4)      // 512 float4 per tile
#define MAX_B 8192
#define GRID_MAIN 1216             // 152 SMs * 8 CTAs

__device__ float g_row[MAX_B];     // per-row integral accumulators

__global__ void zero_rows_kernel(int B) {
    int i = blockIdx.x * blockDim.x + threadIdx.x;
    if (i < B) g_row[i] = 0.0f;
}

__global__ __launch_bounds__(THREADS)
void strain_tiles_kernel(const float* __restrict__ y_pred,
                         const float* __restrict__ y_true,
                         const float* __restrict__ x,
                         const int* __restrict__ fidx,
                         int B, int N, int tiles_per_row) {
    const float4* __restrict__ x4 = (const float4*)x;
    const int total_tiles = B * tiles_per_row;
    const int lane = threadIdx.x & 31;
    const int wid  = threadIdx.x >> 5;
    __shared__ float warp_sums[THREADS / 32];

    for (int tile = blockIdx.x; tile < total_tiles; tile += GRID_MAIN) {
        const int r = tile / tiles_per_row;
        const int c = tile - r * tiles_per_row;
        const int c0 = c * CHUNK;                  // first element of this tile

        int idx = fidx[r];
        idx = min(max(idx, 0), N - 1);
        if (c0 > idx) continue;                    // dead tile

        const int c1 = min(c0 + CHUNK, N);         // one past last element
        const int ncg = idx >> 2;                  // global clean vec count
        const int v0 = c0 >> 2;
        const int vend = min(v0 + CHUNK_VEC, ncg); // clean vecs in this tile

        const float* __restrict__ p = y_pred + (size_t)r * N;
        const float* __restrict__ t = y_true + (size_t)r * N;
        const float4* __restrict__ p4 = (const float4*)p;
        const float4* __restrict__ t4 = (const float4*)t;

        float acc = 0.0f;

        // Clean interior vectors: central-difference weights, all lanes j < idx.
        for (int v = v0 + threadIdx.x; v < vend; v += THREADS) {
            const int j0 = v << 2;
            float4 a  = p4[v];
            float4 b  = t4[v];
            float4 xv = x4[v];                     // L1/L2-resident
            float xm1 = x[j0 ? (j0 - 1) : 0];      // clamp: j0==0 -> x[0]
            float xp4 = x[j0 + 4];                 // j0+3 < idx <= N-1, safe

            acc = fmaf(0.5f * (xv.y - xm1),  a.x - b.x, acc);
            acc = fmaf(0.5f * (xv.z - xv.x), a.y - b.y, acc);
            acc = fmaf(0.5f * (xv.w - xv.y), a.z - b.z, acc);
            acc = fmaf(0.5f * (xp4  - xv.z), a.w - b.w, acc);
        }

        // Boundary scalars in this tile: j in [max(4*ncg, c0), min(idx, c1-1)].
        const int jstart = max(ncg << 2, c0);
        const int jend   = min(idx, c1 - 1);
        for (int j = jstart + threadIdx.x; j <= jend; j += THREADS) {
            float left  = (j > 0)   ? (x[j] - x[j - 1]) : 0.0f;
            float right = (j < idx) ? (x[j + 1] - x[j]) : 0.0f;
            acc = fmaf(0.5f * (left + right), p[j] - t[j], acc);
        }

        // Block reduction for this tile
        #pragma unroll
        for (int off = 16; off > 0; off >>= 1)
            acc += __shfl_xor_sync(0xFFFFFFFFu, acc, off);
        if (lane == 0) warp_sums[wid] = acc;
        __syncthreads();
        if (threadIdx.x == 0) {
            float s = 0.0f;
            #pragma unroll
            for (int w = 0; w < THREADS / 32; w++) s += warp_sums[w];
            atomicAdd(&g_row[r], s);
        }
        __syncthreads();   // protect warp_sums before next tile's writes
    }
}

__global__ __launch_bounds__(256)
void finalize_kernel(float* __restrict__ out, int B, float inv_B) {
    float acc = 0.0f;
    for (int i = threadIdx.x; i < B; i += 256) {
        float v = g_row[i];
        acc = fmaf(v, v, acc);
    }
    #pragma unroll
    for (int off = 16; off > 0; off >>= 1)
        acc += __shfl_xor_sync(0xFFFFFFFFu, acc, off);

    __shared__ float warp_sums[8];
    const int lane = threadIdx.x & 31;
    const int wid  = threadIdx.x >> 5;
    if (lane == 0) warp_sums[wid] = acc;
    __syncthreads();
    if (threadIdx.x == 0) {
        float s = 0.0f;
        #pragma unroll
        for (int w = 0; w < 8; w++) s += warp_sums[w];
        out[0] = s * inv_B;
    }
}

extern "C" void kernel_launch(void* const* d_in, const int* in_sizes, int n_in,
                              void* d_out, int out_size) {
    const float* y_pred = (const float*)d_in[0];
    const float* y_true = (const float*)d_in[1];
    const float* x_vals = (const float*)d_in[2];
    const int*   fidx   = (const int*)d_in[3];
    float* out = (float*)d_out;

    const int B = in_sizes[3];   // fracture_idx element count
    const int N = in_sizes[2];   // x_values element count
    const int tiles_per_row = (N + CHUNK - 1) / CHUNK;
    const int total_tiles = B * tiles_per_row;
    const int grid = total_tiles < GRID_MAIN ? total_tiles : GRID_MAIN;

    zero_rows_kernel<<<(B + 255) / 256, 256>>>(B);
    strain_tiles_kernel<<<grid, THREADS>>>(y_pred, y_true, x_vals, fidx,
                                           B, N, tiles_per_row);
    finalize_kernel<<<1, 256>>>(out, B, 1.0f / (float)B);
}

// round 12
// speedup vs baseline: 1.9916x; 1.9916x over previous
#include <cuda_runtime.h>

// CustomStrainEnergyLoss: mean over B of (trapz(y_pred - y_true, x, segments j < idx))^2
// Element-weight form: integral_r = sum_{j=0}^{idx_r} w(j)*(p[j]-t[j]),
//   w(j) = 0.5*((j>0 ? x[j]-x[j-1] : 0) + (j<idx ? x[j+1]-x[j] : 0))
// For interior j (j < idx): w(j) = 0.5*(x[j+1]-x[max(j-1,0)])  (clamp -> j=0 exact).
// Weights are ROW-INVARIANT: precomputed once into g_w (32KB, L2-resident).
//
// ROUND 12: exact R2 structure (block-per-row, 256 thr, simple loop — proven
// best at 28.4us / DRAM 61.6%) with ONE change: the interior loop reads the
// precomputed w stream instead of recomputing weights from x. This cuts LDG
// issues per vector-iteration from 5 (p4,t4,x4,+2 scalar x) to 3 (p4,t4,w4),
// relieving the 52.7%-busy L1/LSU path that throttles DRAM-bound load issue.

#define THREADS 256
#define MAX_N 8192

__device__ float g_w[MAX_N];   // interior trapezoid weights, w[j] valid for j < N-1

__global__ void prep_kernel(const float* __restrict__ x, float* out, int N) {
    int j = blockIdx.x * blockDim.x + threadIdx.x;
    if (j == 0) out[0] = 0.0f;           // zero scalar output in same launch
    if (j < N - 1) {
        float xm1 = x[j > 0 ? j - 1 : 0];
        g_w[j] = 0.5f * (x[j + 1] - xm1);
    }
}

__global__ __launch_bounds__(THREADS)
void strain_loss_kernel(const float* __restrict__ y_pred,
                        const float* __restrict__ y_true,
                        const float* __restrict__ x,
                        const int* __restrict__ fidx,
                        float* __restrict__ out,
                        int N, float inv_B) {
    const int r = blockIdx.x;
    int idx = fidx[r];
    idx = min(max(idx, 0), N - 1);
    const int nc = idx >> 2;   // clean interior float4 vectors: lanes j <= 4*nc-1 < idx

    const float* __restrict__ p = y_pred + (size_t)r * N;
    const float* __restrict__ t = y_true + (size_t)r * N;
    const float4* __restrict__ p4 = (const float4*)p;
    const float4* __restrict__ t4 = (const float4*)t;
    const float4* __restrict__ w4 = (const float4*)g_w;

    float acc = 0.0f;

    // Interior loop: 3 clean LDG.128 streams, 4 FMAs. (w is L2-resident.)
    for (int v = threadIdx.x; v < nc; v += THREADS) {
        float4 a = p4[v];
        float4 b = t4[v];
        float4 c = w4[v];
        acc = fmaf(c.x, a.x - b.x, acc);
        acc = fmaf(c.y, a.y - b.y, acc);
        acc = fmaf(c.z, a.z - b.z, acc);
        acc = fmaf(c.w, a.w - b.w, acc);
    }

    // Scalar tail: elements [4*nc, idx] (at most 4), exact trapezoid weights.
    for (int j = (nc << 2) + threadIdx.x; j <= idx; j += THREADS) {
        float left  = (j > 0)   ? (x[j] - x[j - 1]) : 0.0f;
        float right = (j < idx) ? (x[j + 1] - x[j]) : 0.0f;
        acc = fmaf(0.5f * (left + right), p[j] - t[j], acc);
    }

    // Block reduction: warp shuffle then shared memory (8 warps)
    #pragma unroll
    for (int off = 16; off > 0; off >>= 1)
        acc += __shfl_xor_sync(0xFFFFFFFFu, acc, off);

    __shared__ float warp_sums[THREADS / 32];
    const int lane = threadIdx.x & 31;
    const int wid  = threadIdx.x >> 5;
    if (lane == 0) warp_sums[wid] = acc;
    __syncthreads();

    if (wid == 0) {
        float s = (lane < THREADS / 32) ? warp_sums[lane] : 0.0f;
        #pragma unroll
        for (int off = 4; off > 0; off >>= 1)
            s += __shfl_xor_sync(0xFFFFFFFFu, s, off);
        if (lane == 0)
            atomicAdd(out, s * s * inv_B);   // err_sq pre-scaled by 1/B
    }
}

extern "C" void kernel_launch(void* const* d_in, const int* in_sizes, int n_in,
                              void* d_out, int out_size) {
    const float* y_pred = (const float*)d_in[0];
    const float* y_true = (const float*)d_in[1];
    const float* x_vals = (const float*)d_in[2];
    const int*   fidx   = (const int*)d_in[3];
    float* out = (float*)d_out;

    const int B = in_sizes[3];                                // fracture_idx count
    const int N = in_sizes[2] > MAX_N ? MAX_N : in_sizes[2];  // x_values count

    prep_kernel<<<(N + 255) / 256, 256>>>(x_vals, out, N);
    strain_loss_kernel<<<B, THREADS>>>(y_pred, y_true, x_vals, fidx, out,
                                       N, 1.0f / (float)B);
}